// round 17
// baseline (speedup 1.0000x reference)
#include <cuda_runtime.h>
#include <cuda_fp16.h>
#include <cstdint>

#define NTOK 16384
#define DIM  1024
#define NH   16

// ---------------- scratch (allocation-free __device__ globals) ----------------
__device__ __half g_proj[9][(size_t)NTOK * DIM];         // fp16 projections
__device__ __half g_in_hi[3][(size_t)NTOK * DIM];        // q,k,v fp16 (row-major)
__device__ __half g_avg_hi[(size_t)NTOK * DIM];          // averaged attn out fp16
__device__ __half g_w_hi[10][(size_t)DIM * DIM];         // weights fp16 (row-major [N,K])

__device__ __constant__ int c_ws[9] = {0,5,7, 2,1,6, 4,3,8};   // weight sel [a*3+kb]
__device__ __constant__ int c_os[9] = {0,5,7, 2,4,6, 1,3,8};   // proj out sel

__device__ __forceinline__ uint32_t smem_u32(const void* p) {
    uint32_t a;
    asm("{ .reg .u64 t; cvta.to.shared.u64 t, %1; cvt.u32.u64 %0, t; }" : "=r"(a) : "l"(p));
    return a;
}

#define MMA16816(C, a0, a1, a2, a3, b0, b1)                                          \
    asm volatile("mma.sync.aligned.m16n8k16.row.col.f32.f16.f16.f32 "                \
        "{%0,%1,%2,%3}, {%4,%5,%6,%7}, {%8,%9}, {%0,%1,%2,%3};"                      \
        : "+f"((C)[0]), "+f"((C)[1]), "+f"((C)[2]), "+f"((C)[3])                     \
        : "r"(a0), "r"(a1), "r"(a2), "r"(a3), "r"(b0), "r"(b1))

// pack two f32 -> f16x2 (lo = first arg)
__device__ __forceinline__ uint32_t pack_h2(float lo, float hi) {
    uint32_t d;
    asm("cvt.rn.f16x2.f32 %0, %1, %2;" : "=r"(d) : "f"(hi), "f"(lo));
    return d;
}

// FMA-pipe exp: 2^n split via magic number + degree-6 Horner. No MUFU.
__device__ __forceinline__ float fast_exp(float x) {
    float t = fmaf(x, 1.4426950408889634f, 12582912.0f);
    float n = t - 12582912.0f;
    int ni = __float_as_int(t);
    float r = fmaf(n, -0.6931471805599453f, x);
    float p = 1.3888889e-3f;
    p = fmaf(p, r, 8.3333333e-3f);
    p = fmaf(p, r, 4.1666667e-2f);
    p = fmaf(p, r, 1.6666667e-1f);
    p = fmaf(p, r, 0.5f);
    p = fmaf(p, r, 1.0f);
    p = fmaf(p, r, 1.0f);
    int sc = (ni - 0x4B400000 + 127) << 23;
    return p * __int_as_float(sc);
}

// ---------------- fused fp32 -> fp16 convert: all 13 tensors, ONE launch ----------
#define IN2 ((size_t)NTOK * 512)
#define W2  ((size_t)DIM * 512)

__global__ void decompose_all(
    const float* __restrict__ q, const float* __restrict__ k, const float* __restrict__ v,
    const float* __restrict__ w0, const float* __restrict__ w1, const float* __restrict__ w2,
    const float* __restrict__ w3, const float* __restrict__ w4, const float* __restrict__ w5,
    const float* __restrict__ w6, const float* __restrict__ w7, const float* __restrict__ w8,
    const float* __restrict__ w9)
{
    size_t i = (size_t)blockIdx.x * blockDim.x + threadIdx.x;
    const size_t NIN = 3 * IN2;
    const float* src;
    __half* dst;
    size_t off;
    if (i < NIN) {
        int sel = (int)(i / IN2);
        off = (i - (size_t)sel * IN2) * 2;
        src = (sel == 0) ? q : (sel == 1) ? k : v;
        dst = g_in_hi[sel];
    } else {
        size_t j = i - NIN;
        if (j >= 10 * W2) return;
        int sel = (int)(j / W2);
        off = (j - (size_t)sel * W2) * 2;
        const float* ws[10] = {w0, w1, w2, w3, w4, w5, w6, w7, w8, w9};
        src = ws[sel];
        dst = g_w_hi[sel];
    }
    float2 x = *(const float2*)(src + off);
    __half2 hv;
    hv.x = __float2half_rn(x.x);
    hv.y = __float2half_rn(x.y);
    *(__half2*)(dst + off) = hv;
}

// ---------------- fp16 HMMA GEMM: 128 threads, warp tile 64x64, BK=64, 2-stage ----
// 3 CTAs/SM target: smem 73.7KB/CTA, regs <= 170.
#define ROWB 144
#define TILEB (128 * ROWB)
#define STAGEB (2 * TILEB)
#define NSTAGE 2
#define DYN_SMEM (NSTAGE * STAGEB)   // 73728 B
#define NC 16

__global__ __launch_bounds__(128, 3)
void gemm_mma(int mode,
              const float* __restrict__ b0, const float* __restrict__ b1, const float* __restrict__ b2,
              const float* __restrict__ b3, const float* __restrict__ b4, const float* __restrict__ b5,
              const float* __restrict__ b6, const float* __restrict__ b7, const float* __restrict__ b8,
              const float* __restrict__ bfin, float* __restrict__ dext)
{
    extern __shared__ __align__(16) char dsm[];

    const int tid = threadIdx.x;
    const int wid = tid >> 5;
    const int lane = tid & 31;
    const int kb = blockIdx.x >> 3;
    const int xb = blockIdx.x & 7;
    const int by = blockIdx.y;
    const int az = blockIdx.z;

    const __half* Ahi;
    const float* bias;
    int wsel, osel;
    if (mode == 0) {
        const int idx = az * 3 + kb;
        wsel = c_ws[idx];
        osel = c_os[idx];
        Ahi = g_in_hi[az];
        bias = (idx == 0) ? b0 : (idx == 1) ? b1 : (idx == 2) ? b2 :
               (idx == 3) ? b3 : (idx == 4) ? b4 : (idx == 5) ? b5 :
               (idx == 6) ? b6 : (idx == 7) ? b7 : b8;
    } else {
        wsel = 9; osel = 0;
        Ahi = g_avg_hi;
        bias = bfin;
    }
    const __half* Bhi = g_w_hi[wsel];

    const uint32_t smu = smem_u32(dsm);

    // loader: base pointer + compile-time offsets (regs stay low)
    const __half* gAp = Ahi + (size_t)(by * 128 + (tid >> 3)) * DIM + (tid & 7) * 8;
    const __half* gBp = Bhi + (size_t)(xb * 128 + (tid >> 3)) * DIM + (tid & 7) * 8;
    const uint32_t sOb = (uint32_t)((tid >> 3) * ROWB + (tid & 7) * 16);

    const int warp_m = (wid >> 1) * 64;
    const int warp_n = (wid & 1) * 64;
    const int quad = lane >> 3, l7 = lane & 7;
    const uint32_t aoff = (uint32_t)((warp_m + (quad & 1) * 8 + l7) * ROWB + (quad >> 1) * 16);
    const uint32_t boff = (uint32_t)((warp_n + (quad >> 1) * 8 + l7) * ROWB + (quad & 1) * 16);

    float acc[4][8][4];
    #pragma unroll
    for (int i = 0; i < 4; i++)
        #pragma unroll
        for (int j = 0; j < 8; j++)
            #pragma unroll
            for (int r = 0; r < 4; r++) acc[i][j][r] = 0.f;

    auto issue_chunk = [&](int c, int stg) {
        const int ko = c << 6;
        const uint32_t sb = smu + stg * STAGEB + sOb;
        const __half* ga = gAp + ko;
        const __half* gb = gBp + ko;
        #pragma unroll
        for (int j = 0; j < 8; j++) {
            asm volatile("cp.async.cg.shared.global [%0], [%1], 16;"
                         :: "r"(sb + j * (16 * ROWB)), "l"(ga + (size_t)j * 16 * DIM));
            asm volatile("cp.async.cg.shared.global [%0], [%1], 16;"
                         :: "r"(sb + TILEB + j * (16 * ROWB)), "l"(gb + (size_t)j * 16 * DIM));
        }
        asm volatile("cp.async.commit_group;");
    };

    issue_chunk(0, 0);

    for (int c = 0; c < NC; c++) {
        asm volatile("cp.async.wait_group 0;");
        __syncthreads();
        if (c + 1 < NC) issue_chunk(c + 1, (c + 1) & 1);

        const uint32_t sb = smu + (c & 1) * STAGEB;
        #pragma unroll
        for (int ks = 0; ks < 4; ks++) {
            uint32_t bf[4][4];
            #pragma unroll
            for (int nt = 0; nt < 4; nt++) {
                uint32_t addr = sb + TILEB + boff + nt * (16 * ROWB) + ks * 32;
                asm volatile("ldmatrix.sync.aligned.m8n8.x4.shared.b16 {%0,%1,%2,%3}, [%4];"
                             : "=r"(bf[nt][0]), "=r"(bf[nt][1]), "=r"(bf[nt][2]), "=r"(bf[nt][3])
                             : "r"(addr));
            }
            uint32_t af[4][4];
            #pragma unroll
            for (int mt = 0; mt < 4; mt++) {
                uint32_t addr = sb + aoff + mt * (16 * ROWB) + ks * 32;
                asm volatile("ldmatrix.sync.aligned.m8n8.x4.shared.b16 {%0,%1,%2,%3}, [%4];"
                             : "=r"(af[mt][0]), "=r"(af[mt][1]), "=r"(af[mt][2]), "=r"(af[mt][3])
                             : "r"(addr));
            }
            #pragma unroll
            for (int mt = 0; mt < 4; mt++)
                #pragma unroll
                for (int n8 = 0; n8 < 8; n8++)
                    MMA16816(acc[mt][n8],
                             af[mt][0], af[mt][1], af[mt][2], af[mt][3],
                             bf[n8 >> 1][(n8 & 1) * 2 + 0], bf[n8 >> 1][(n8 & 1) * 2 + 1]);
        }
    }

    const int erow0 = by * 128 + warp_m + (lane >> 2);
    const int ecol0 = xb * 128 + warp_n + 2 * (lane & 3);
    if (mode == 0) {
        __half* Ch = g_proj[osel];
        #pragma unroll
        for (int mt = 0; mt < 4; mt++) {
            #pragma unroll
            for (int n8 = 0; n8 < 8; n8++) {
                const int col = ecol0 + n8 * 8;
                const float bb0 = bias[col], bb1 = bias[col + 1];
                #pragma unroll
                for (int h = 0; h < 2; h++) {
                    const int row = erow0 + mt * 16 + h * 8;
                    __half2 hv;
                    hv.x = __float2half_rn(acc[mt][n8][2 * h + 0] + bb0);
                    hv.y = __float2half_rn(acc[mt][n8][2 * h + 1] + bb1);
                    *(__half2*)(Ch + (size_t)row * DIM + col) = hv;
                }
            }
        }
    } else {
        #pragma unroll
        for (int mt = 0; mt < 4; mt++) {
            #pragma unroll
            for (int n8 = 0; n8 < 8; n8++) {
                const int col = ecol0 + n8 * 8;
                const float bb0 = bias[col], bb1 = bias[col + 1];
                #pragma unroll
                for (int h = 0; h < 2; h++) {
                    const int row = erow0 + mt * 16 + h * 8;
                    float2 v;
                    v.x = fmaxf(acc[mt][n8][2 * h + 0] + bb0, 0.f);
                    v.y = fmaxf(acc[mt][n8][2 * h + 1] + bb1, 0.f);
                    *(float2*)(dext + (size_t)row * DIM + col) = v;
                }
            }
        }
    }
}

// ---------------- tensor-core attention: in-register softmax (unchanged R16) ------
#define SM_QT   0                      // 64*24 half = 3072 B
#define SM_KT   3072                   // 64*24 half = 3072 B
#define SM_VH   6144                   // 16*36 u32  = 2304 B
#define SM_PS   8448                   // 64*5 float = 1280 B
#define SM_INV  9728                   // 64 float   = 256 B
#define SM_ATTN 9984

__global__ __launch_bounds__(128)
void attn_kernel()
{
    __shared__ __align__(16) unsigned char smb[SM_ATTN];
    __half*   Qt   = (__half*)(smb + SM_QT);
    __half*   Kt   = (__half*)(smb + SM_KT);
    uint32_t* Vh   = (uint32_t*)(smb + SM_VH);
    float*    Psum = (float*)(smb + SM_PS);
    float*    invs = (float*)(smb + SM_INV);

    const int n = blockIdx.x;
    const int t = threadIdx.x;
    const int w = t >> 5;
    const int l = t & 31;
    const int r = l >> 2;
    const int cq = l & 3;

    float oacc[2][4];
    #pragma unroll
    for (int nt = 0; nt < 2; nt++)
        #pragma unroll
        for (int j = 0; j < 4; j++) oacc[nt][j] = 0.f;

    for (int a = 0; a < 3; a++) {
        const uint4* Qp = (const uint4*)(g_proj[3 * a + 0] + (size_t)n * DIM);
        const uint4* Kp = (const uint4*)(g_proj[3 * a + 1] + (size_t)n * DIM);
        const uint4* Vp = (const uint4*)(g_proj[3 * a + 2] + (size_t)n * DIM);

        {
            const int h = t >> 3;
            const int d0 = (t & 7) * 8;

            uint4 qv = Qp[t];
            uint32_t qa[4] = {qv.x, qv.y, qv.z, qv.w};
            #pragma unroll
            for (int j = 0; j < 4; j++) {
                __half2 p = *(__half2*)&qa[j];
                Qt[(d0 + 2 * j) * 24 + h]     = p.x;
                Qt[(d0 + 2 * j + 1) * 24 + h] = p.y;
            }

            uint4 kv = Kp[t];
            uint32_t ka[4] = {kv.x, kv.y, kv.z, kv.w};
            #pragma unroll
            for (int j = 0; j < 4; j++) {
                __half2 p = *(__half2*)&ka[j];
                Kt[(d0 + 2 * j) * 24 + h]     = p.x;
                Kt[(d0 + 2 * j + 1) * 24 + h] = p.y;
            }

            uint4 vv = Vp[t];
            uint32_t va[4] = {vv.x, vv.y, vv.z, vv.w};
            #pragma unroll
            for (int j = 0; j < 4; j++)
                Vh[h * 36 + (d0 >> 1) + j] = va[j];
        }
        __syncthreads();

        float sc[8][4];
        {
            uint32_t a0 = *(uint32_t*)&Qt[(16 * w + r) * 24 + 2 * cq];
            uint32_t a1 = *(uint32_t*)&Qt[(16 * w + r + 8) * 24 + 2 * cq];
            uint32_t a2 = *(uint32_t*)&Qt[(16 * w + r) * 24 + 2 * cq + 8];
            uint32_t a3 = *(uint32_t*)&Qt[(16 * w + r + 8) * 24 + 2 * cq + 8];
            #pragma unroll
            for (int nt = 0; nt < 8; nt++) {
                const int e0 = nt * 8;
                uint32_t b0 = *(uint32_t*)&Kt[(e0 + r) * 24 + 2 * cq];
                uint32_t b1 = *(uint32_t*)&Kt[(e0 + r) * 24 + 2 * cq + 8];
                float c[4] = {0.f, 0.f, 0.f, 0.f};
                MMA16816(c, a0, a1, a2, a3, b0, b1);
                sc[nt][0] = fast_exp(c[0] * 0.125f);
                sc[nt][1] = fast_exp(c[1] * 0.125f);
                sc[nt][2] = fast_exp(c[2] * 0.125f);
                sc[nt][3] = fast_exp(c[3] * 0.125f);
            }
        }

        #pragma unroll
        for (int nt = 0; nt < 8; nt++) {
            float p0 = sc[nt][0] + sc[nt][2];
            float p1 = sc[nt][1] + sc[nt][3];
            p0 += __shfl_xor_sync(0xFFFFFFFF, p0, 4);
            p1 += __shfl_xor_sync(0xFFFFFFFF, p1, 4);
            p0 += __shfl_xor_sync(0xFFFFFFFF, p0, 8);
            p1 += __shfl_xor_sync(0xFFFFFFFF, p1, 8);
            p0 += __shfl_xor_sync(0xFFFFFFFF, p0, 16);
            p1 += __shfl_xor_sync(0xFFFFFFFF, p1, 16);
            if (r == 0) {
                const int e = nt * 8 + 2 * cq;
                Psum[e * 5 + w]       = p0;
                Psum[(e + 1) * 5 + w] = p1;
            }
        }
        __syncthreads();

        if (t < 64)
            invs[t] = 1.f / (Psum[t * 5 + 0] + Psum[t * 5 + 1] +
                             Psum[t * 5 + 2] + Psum[t * 5 + 3]);
        __syncthreads();

        uint32_t wlo[8], whi[8];
        #pragma unroll
        for (int nt = 0; nt < 8; nt++) {
            const int e = nt * 8 + 2 * cq;
            const float iv0 = invs[e], iv1 = invs[e + 1];
            wlo[nt] = pack_h2(sc[nt][0] * iv0, sc[nt][1] * iv1);
            whi[nt] = pack_h2(sc[nt][2] * iv0, sc[nt][3] * iv1);
        }
        #pragma unroll
        for (int ks = 0; ks < 4; ks++) {
            #pragma unroll
            for (int nt = 0; nt < 2; nt++) {
                const int h0 = nt * 8;
                uint32_t vh0 = Vh[(h0 + r) * 36 + 8 * ks + cq];
                uint32_t vh1 = Vh[(h0 + r) * 36 + 8 * ks + cq + 4];
                MMA16816(oacc[nt], wlo[2 * ks], whi[2 * ks],
                         wlo[2 * ks + 1], whi[2 * ks + 1], vh0, vh1);
            }
        }
        __syncthreads();
    }

    __half* osh = (__half*)smb;
    {
        #pragma unroll
        for (int nt = 0; nt < 2; nt++) {
            const int h = nt * 8 + 2 * cq;
            const int d = 16 * w + r;
            osh[h * 64 + d]           = __float2half_rn(oacc[nt][0] * (1.f / 3.f));
            osh[(h + 1) * 64 + d]     = __float2half_rn(oacc[nt][1] * (1.f / 3.f));
            osh[h * 64 + d + 8]       = __float2half_rn(oacc[nt][2] * (1.f / 3.f));
            osh[(h + 1) * 64 + d + 8] = __float2half_rn(oacc[nt][3] * (1.f / 3.f));
        }
    }
    __syncthreads();

    uint4* dst = (uint4*)(g_avg_hi + (size_t)n * DIM);
    const uint4* srcv = (const uint4*)osh;
    dst[t] = srcv[t];
}

// ---------------------------------------------------------------------------
extern "C" void kernel_launch(void* const* d_in, const int* in_sizes, int n_in,
                              void* d_out, int out_size)
{
    (void)in_sizes; (void)n_in; (void)out_size;

    cudaFuncSetAttribute(gemm_mma, cudaFuncAttributeMaxDynamicSharedMemorySize, DYN_SMEM);

    {
        const size_t total = 3 * IN2 + 10 * W2;
        const int blocks = (int)((total + 255) / 256);
        decompose_all<<<blocks, 256>>>(
            (const float*)d_in[0], (const float*)d_in[1], (const float*)d_in[2],
            (const float*)d_in[3], (const float*)d_in[5], (const float*)d_in[7],
            (const float*)d_in[9], (const float*)d_in[11], (const float*)d_in[13],
            (const float*)d_in[15], (const float*)d_in[17], (const float*)d_in[19],
            (const float*)d_in[21]);
    }

    dim3 gproj(24, 128, 3);
    gemm_mma<<<gproj, 128, DYN_SMEM>>>(0,
        (const float*)d_in[4], (const float*)d_in[14], (const float*)d_in[18],
        (const float*)d_in[8], (const float*)d_in[6], (const float*)d_in[16],
        (const float*)d_in[12], (const float*)d_in[10], (const float*)d_in[20],
        nullptr, nullptr);

    attn_kernel<<<NTOK, 128>>>();

    dim3 gfin(8, 128, 1);
    gemm_mma<<<gfin, 128, DYN_SMEM>>>(1,
        nullptr, nullptr, nullptr, nullptr, nullptr, nullptr,
        nullptr, nullptr, nullptr,
        (const float*)d_in[22], (float*)d_out);
}